// round 16
// baseline (speedup 1.0000x reference)
#include <cuda_runtime.h>

// Problem constants
#define Bsz 4096
#define Vn  50
#define Fn  15
#define Hn  256
#define Gn  1024   // 4*H

// ---------------- scratch (static device globals; no allocation) ----------
__device__ float g_h1a[Bsz * Hn];
__device__ float g_h1b[Bsz * Hn];
__device__ float g_c1 [Bsz * Hn];
__device__ float g_h2a[Bsz * Hn];
__device__ float g_h2b[Bsz * Hn];
__device__ float g_c2 [Bsz * Hn];
__device__ float g_m1[Bsz * 1024];
__device__ float g_m2[Bsz * 1024];
__device__ float g_m3[Bsz * 512];
__device__ float g_m4[Bsz * 256];
__device__ float g_pre2[Bsz * Gn];
// pi-head partial dot-products: [parity][bx=8][m=4096]
__device__ float g_pipart[2][8][Bsz];

typedef unsigned long long ull;

__device__ __forceinline__ void dup2(ull& d, float s) {
    asm("mov.b64 %0,{%1,%1};" : "=l"(d) : "f"(s));
}
__device__ __forceinline__ void ffma2(ull& d, ull a, ull b) {
    asm("fma.rn.f32x2 %0,%1,%2,%0;" : "+l"(d) : "l"(a), "l"(b));
}
__device__ __forceinline__ float2 u2f(ull u) {
    float2 f; asm("mov.b64 {%0,%1},%2;" : "=f"(f.x), "=f"(f.y) : "l"(u)); return f;
}
// Fast-math gates — validated (rounds 11/13/15: rel_err ~7e-6 end-to-end).
__device__ __forceinline__ float fsig(float x) {
    return __fdividef(1.0f, 1.0f + __expf(-x));
}
__device__ __forceinline__ float ftanh(float x) {
    return 1.0f - __fdividef(2.0f, __expf(2.0f * x) + 1.0f);
}

// ---------------- zero the recurrent states --------------------------------
__global__ void zero_states_kernel() {
    int idx = blockIdx.x * blockDim.x + threadIdx.x;
    if (idx < Bsz * Hn) {
        g_h1a[idx] = 0.f; g_c1[idx] = 0.f;
        g_h2a[idx] = 0.f; g_c2[idx] = 0.f;
    }
}

// ---------------- fused SGEMM (K-tile 32, split staging, pi fusion) ---------
// Block tile 128x128, 256 threads, quadrant 8x8 microtile, f32x2 FMA.
// K-tile 32 (dynamic smem 64KB, double-buffered) halves the barrier count vs
// round-15's K-tile 16. Staging regs stay at 16 via SPLIT staging: prefetch
// A-next during kk 0..15, store + prefetch W-next during kk 16..31.
// REMAP: weight row = ((n&3)<<8)|(n>>2). EPI: 0 bias, 1 relu, 2 LSTM,
// 3 LSTM + pi partial (+ finalize previous step's pi in bx==0 CTAs).
#define KT 32
#define ABUF(b) (smem + (b) * (KT * 128))
#define BBUF(b) (smem + 2 * (KT * 128) + (b) * (KT * 128))

template <int EPI, int REMAP, int W4>
__global__ void __launch_bounds__(256, 2) gemm5(
    const float* __restrict__ A,  int lda,
    const float* __restrict__ W,  int ldw, int K,
    const float* __restrict__ A2, int lda2,
    const float* __restrict__ W2, int ldw2, int K2,
    const float* __restrict__ b1, const float* __restrict__ b2,
    const float* __restrict__ addmat,
    float* __restrict__ C, int N,
    float* __restrict__ cSt,
    const float* __restrict__ piW, const float* __restrict__ pib,
    float* __restrict__ outv,
    float* __restrict__ partCur, const float* __restrict__ partPrev,
    int vprev)
{
    extern __shared__ float smem[];

    const int tid = threadIdx.x;
    const int tx = tid & 15;
    const int ty = tid >> 4;
    const int m0 = blockIdx.y * 128;
    const int n0 = blockIdx.x * 128;

    // ---- finalize previous step's pi output (bx==0 CTAs, independent) ----
    if (EPI == 3 && blockIdx.x == 0 && vprev >= 0 && tid < 128) {
        int m = m0 + tid;
        float s = pib[0];
#pragma unroll
        for (int b = 0; b < 8; b++) s += partPrev[b * Bsz + m];
        outv[(size_t)m * Vn + vprev] = ftanh(s);
    }

    const int lr = tid >> 1;          // 0..127 staging row
    const int lc = (tid & 1) * 16;    // 0 or 16 staging k-half
    const int gn = n0 + lr;
    const int wrow = REMAP ? (((gn & 3) << 8) | (gn >> 2)) : gn;
    const float* Ap = A + (size_t)(m0 + lr) * lda + lc;
    const float* Wp = W + (size_t)wrow * ldw + lc;

    ull acc[8][4];
#pragma unroll
    for (int i = 0; i < 8; i++)
#pragma unroll
        for (int j = 0; j < 4; j++) acc[i][j] = 0ull;

    float st[16];

    // ---- stage tile 0 ----
    {
        float* As0 = ABUF(0);
        float* Bs0 = BBUF(0);
#pragma unroll
        for (int q = 0; q < 4; q++) {
            float4 v = *(const float4*)(Ap + 4 * q);
            st[4 * q] = v.x; st[4 * q + 1] = v.y; st[4 * q + 2] = v.z; st[4 * q + 3] = v.w;
        }
#pragma unroll
        for (int i = 0; i < 16; i++) As0[(lc + i) * 128 + lr] = st[i];
        if (W4) {
#pragma unroll
            for (int q = 0; q < 4; q++) {
                float4 v = *(const float4*)(Wp + 4 * q);
                st[4 * q] = v.x; st[4 * q + 1] = v.y; st[4 * q + 2] = v.z; st[4 * q + 3] = v.w;
            }
        } else {
#pragma unroll
            for (int i = 0; i < 16; i++) st[i] = Wp[i];
        }
#pragma unroll
        for (int i = 0; i < 16; i++) Bs0[(lc + i) * 128 + lr] = st[i];
    }
    __syncthreads();

    const int T = K >> 5;   // all K used are multiples of 32
    for (int t = 0; t < T; t++) {
        const int cu = t & 1, nx = cu ^ 1;
        const bool more = (t + 1) < T;
        const float* AsC = ABUF(cu);
        const float* BsC = BBUF(cu);

        // prefetch A-next
        if (more) {
            const float* ap = Ap + (t + 1) * KT;
#pragma unroll
            for (int q = 0; q < 4; q++) {
                float4 v = *(const float4*)(ap + 4 * q);
                st[4 * q] = v.x; st[4 * q + 1] = v.y; st[4 * q + 2] = v.z; st[4 * q + 3] = v.w;
            }
        }
        // ---- compute kk 0..15 ----
#pragma unroll
        for (int kk = 0; kk < 16; kk++) {
            float4 a0 = *(const float4*)&AsC[kk * 128 + ty * 4];
            float4 a1 = *(const float4*)&AsC[kk * 128 + 64 + ty * 4];
            ulonglong2 bq0 = *(const ulonglong2*)&BsC[kk * 128 + tx * 4];
            ulonglong2 bq1 = *(const ulonglong2*)&BsC[kk * 128 + 64 + tx * 4];
            float ar[8] = {a0.x, a0.y, a0.z, a0.w, a1.x, a1.y, a1.z, a1.w};
#pragma unroll
            for (int i = 0; i < 8; i++) {
                ull aa; dup2(aa, ar[i]);
                ffma2(acc[i][0], aa, bq0.x);
                ffma2(acc[i][1], aa, bq0.y);
                ffma2(acc[i][2], aa, bq1.x);
                ffma2(acc[i][3], aa, bq1.y);
            }
        }
        // store A-next, prefetch W-next
        if (more) {
            float* AsN = ABUF(nx);
#pragma unroll
            for (int i = 0; i < 16; i++) AsN[(lc + i) * 128 + lr] = st[i];
            const float* wp = Wp + (t + 1) * KT;
            if (W4) {
#pragma unroll
                for (int q = 0; q < 4; q++) {
                    float4 v = *(const float4*)(wp + 4 * q);
                    st[4 * q] = v.x; st[4 * q + 1] = v.y; st[4 * q + 2] = v.z; st[4 * q + 3] = v.w;
                }
            } else {
#pragma unroll
                for (int i = 0; i < 16; i++) st[i] = wp[i];
            }
        }
        // ---- compute kk 16..31 ----
#pragma unroll
        for (int kk = 16; kk < 32; kk++) {
            float4 a0 = *(const float4*)&AsC[kk * 128 + ty * 4];
            float4 a1 = *(const float4*)&AsC[kk * 128 + 64 + ty * 4];
            ulonglong2 bq0 = *(const ulonglong2*)&BsC[kk * 128 + tx * 4];
            ulonglong2 bq1 = *(const ulonglong2*)&BsC[kk * 128 + 64 + tx * 4];
            float ar[8] = {a0.x, a0.y, a0.z, a0.w, a1.x, a1.y, a1.z, a1.w};
#pragma unroll
            for (int i = 0; i < 8; i++) {
                ull aa; dup2(aa, ar[i]);
                ffma2(acc[i][0], aa, bq0.x);
                ffma2(acc[i][1], aa, bq0.y);
                ffma2(acc[i][2], aa, bq1.x);
                ffma2(acc[i][3], aa, bq1.y);
            }
        }
        if (more) {
            float* BsN = BBUF(nx);
#pragma unroll
            for (int i = 0; i < 16; i++) BsN[(lc + i) * 128 + lr] = st[i];
            __syncthreads();
        }
    }

    // ---- small-K tail (x_v @ Wih_x.T, K2 <= 15) ----
    // T is even for all K used -> last tile computed from buf 1; tail uses buf 0.
    if (K2 > 0) {
        float* Ta = ABUF(0);
        float* Tb = BBUF(0);
        for (int idx = tid; idx < 128 * K2; idx += 256) {
            int m = idx & 127;
            int k = idx >> 7;
            Ta[k * 128 + m] = A2[(size_t)(m0 + m) * lda2 + k];
            int g2 = n0 + m;
            int wr2 = REMAP ? (((g2 & 3) << 8) | (g2 >> 2)) : g2;
            Tb[k * 128 + m] = W2[(size_t)wr2 * ldw2 + k];
        }
        __syncthreads();
        for (int kk = 0; kk < K2; kk++) {
            float4 a0 = *(const float4*)&Ta[kk * 128 + ty * 4];
            float4 a1 = *(const float4*)&Ta[kk * 128 + 64 + ty * 4];
            ulonglong2 bq0 = *(const ulonglong2*)&Tb[kk * 128 + tx * 4];
            ulonglong2 bq1 = *(const ulonglong2*)&Tb[kk * 128 + 64 + tx * 4];
            float ar[8] = {a0.x, a0.y, a0.z, a0.w, a1.x, a1.y, a1.z, a1.w};
#pragma unroll
            for (int i = 0; i < 8; i++) {
                ull aa; dup2(aa, ar[i]);
                ffma2(acc[i][0], aa, bq0.x);
                ffma2(acc[i][1], aa, bq0.y);
                ffma2(acc[i][2], aa, bq1.x);
                ffma2(acc[i][3], aa, bq1.y);
            }
        }
    }

    // ---- epilogue ----
    float add[8];
    if (EPI < 2 || addmat == nullptr) {
#pragma unroll
        for (int j = 0; j < 8; j++) {
            int n = n0 + ((j < 4) ? (4 * tx + j) : (64 + 4 * tx + (j - 4)));
            int rn = REMAP ? (((n & 3) << 8) | (n >> 2)) : n;
            float t = 0.f;
            if (b1) t += b1[rn];
            if (b2) t += b2[rn];
            add[j] = t;
        }
    }

    if (EPI >= 2) {
        const int hu0 = (n0 >> 2) + tx;
        const int hu1 = hu0 + 16;
        float pw0 = 0.f, pw1 = 0.f;
        if (EPI == 3) { pw0 = piW[hu0]; pw1 = piW[hu1]; }
#pragma unroll
        for (int i = 0; i < 8; i++) {
            int m = m0 + ((i < 4) ? (4 * ty + i) : (64 + 4 * ty + (i - 4)));
            float g[8];
#pragma unroll
            for (int j4 = 0; j4 < 4; j4++) {
                float2 f = u2f(acc[i][j4]);
                g[2 * j4] = f.x; g[2 * j4 + 1] = f.y;
            }
            if (addmat) {
                float4 p0 = *(const float4*)(addmat + (size_t)m * Gn + n0 + 4 * tx);
                float4 p1 = *(const float4*)(addmat + (size_t)m * Gn + n0 + 64 + 4 * tx);
                g[0] += p0.x; g[1] += p0.y; g[2] += p0.z; g[3] += p0.w;
                g[4] += p1.x; g[5] += p1.y; g[6] += p1.z; g[7] += p1.w;
            } else {
#pragma unroll
                for (int j = 0; j < 8; j++) g[j] += add[j];
            }
            size_t c0i = (size_t)m * Hn + hu0;
            size_t c1i = (size_t)m * Hn + hu1;
            float h0, h1;
            {
                float iv = fsig(g[0]), fv = fsig(g[1]);
                float gv = ftanh(g[2]), ov = fsig(g[3]);
                float cn = fv * cSt[c0i] + iv * gv;
                cSt[c0i] = cn;
                h0 = ov * ftanh(cn);
                C[c0i] = h0;
            }
            {
                float iv = fsig(g[4]), fv = fsig(g[5]);
                float gv = ftanh(g[6]), ov = fsig(g[7]);
                float cn = fv * cSt[c1i] + iv * gv;
                cSt[c1i] = cn;
                h1 = ov * ftanh(cn);
                C[c1i] = h1;
            }
            if (EPI == 3) {
                float s = h0 * pw0 + h1 * pw1;
                s += __shfl_xor_sync(0xffffffffu, s, 1);
                s += __shfl_xor_sync(0xffffffffu, s, 2);
                s += __shfl_xor_sync(0xffffffffu, s, 4);
                s += __shfl_xor_sync(0xffffffffu, s, 8);
                if (tx == 0)
                    partCur[(size_t)blockIdx.x * Bsz + m] = s;
            }
        }
    } else {
#pragma unroll
        for (int i = 0; i < 8; i++) {
            int m = m0 + ((i < 4) ? (4 * ty + i) : (64 + 4 * ty + (i - 4)));
            float o[8];
#pragma unroll
            for (int j4 = 0; j4 < 4; j4++) {
                float2 f = u2f(acc[i][j4]);
                o[2 * j4]     = f.x + add[2 * j4];
                o[2 * j4 + 1] = f.y + add[2 * j4 + 1];
            }
            if (EPI == 1) {
#pragma unroll
                for (int j = 0; j < 8; j++) o[j] = fmaxf(o[j], 0.f);
            }
            *(float4*)(C + (size_t)m * N + n0 + 4 * tx)      = make_float4(o[0], o[1], o[2], o[3]);
            *(float4*)(C + (size_t)m * N + n0 + 64 + 4 * tx) = make_float4(o[4], o[5], o[6], o[7]);
        }
    }
}

// ---------------- final pi finalize (step v = Vn-1) --------------------------
__global__ void pi_final_kernel(const float* __restrict__ part,
                                const float* __restrict__ pib,
                                float* __restrict__ out, int v) {
    int m = blockIdx.x * blockDim.x + threadIdx.x;
    if (m >= Bsz) return;
    float s = pib[0];
#pragma unroll
    for (int b = 0; b < 8; b++) s += part[b * Bsz + m];
    out[(size_t)m * Vn + v] = ftanh(s);
}

// ---------------- launch ----------------------------------------------------
#define SMEMB (4 * KT * 128 * 4)   // 65536 bytes

extern "C" void kernel_launch(void* const* d_in, const int* in_sizes, int n_in,
                              void* d_out, int out_size) {
    const float* state  = (const float*)d_in[0];   // [4096, 750]
    const float* l1_Wih = (const float*)d_in[1];   // [1024, 15]
    const float* l1_Whh = (const float*)d_in[2];   // [1024, 256]
    const float* l1_bih = (const float*)d_in[3];
    const float* l1_bhh = (const float*)d_in[4];
    const float* fc1_W  = (const float*)d_in[5];   // [1024, 256]
    const float* fc1_b  = (const float*)d_in[6];
    const float* fc2_W  = (const float*)d_in[7];   // [1024, 1024]
    const float* fc2_b  = (const float*)d_in[8];
    const float* fc3_W  = (const float*)d_in[9];   // [512, 1024]
    const float* fc3_b  = (const float*)d_in[10];
    const float* fc4_W  = (const float*)d_in[11];  // [256, 512]
    const float* fc4_b  = (const float*)d_in[12];
    const float* l2_Wih = (const float*)d_in[13];  // [1024, 271]
    const float* l2_Whh = (const float*)d_in[14];  // [1024, 256]
    const float* l2_bih = (const float*)d_in[15];
    const float* l2_bhh = (const float*)d_in[16];
    const float* pi_W   = (const float*)d_in[17];  // [1, 256]
    const float* pi_b   = (const float*)d_in[18];  // [1]
    float* out = (float*)d_out;                    // [4096, 50]

    float *h1a, *h1b, *c1, *h2a, *h2b, *c2, *m1, *m2, *m3, *m4, *pre2, *pipart;
    cudaGetSymbolAddress((void**)&h1a, g_h1a);
    cudaGetSymbolAddress((void**)&h1b, g_h1b);
    cudaGetSymbolAddress((void**)&c1,  g_c1);
    cudaGetSymbolAddress((void**)&h2a, g_h2a);
    cudaGetSymbolAddress((void**)&h2b, g_h2b);
    cudaGetSymbolAddress((void**)&c2,  g_c2);
    cudaGetSymbolAddress((void**)&m1, g_m1);
    cudaGetSymbolAddress((void**)&m2, g_m2);
    cudaGetSymbolAddress((void**)&m3, g_m3);
    cudaGetSymbolAddress((void**)&m4, g_m4);
    cudaGetSymbolAddress((void**)&pre2, g_pre2);
    cudaGetSymbolAddress((void**)&pipart, g_pipart);

    static bool attr_done = false;
    if (!attr_done) {
        cudaFuncSetAttribute(gemm5<2, 1, 1>, cudaFuncAttributeMaxDynamicSharedMemorySize, SMEMB);
        cudaFuncSetAttribute(gemm5<3, 1, 1>, cudaFuncAttributeMaxDynamicSharedMemorySize, SMEMB);
        cudaFuncSetAttribute(gemm5<1, 0, 1>, cudaFuncAttributeMaxDynamicSharedMemorySize, SMEMB);
        cudaFuncSetAttribute(gemm5<0, 1, 0>, cudaFuncAttributeMaxDynamicSharedMemorySize, SMEMB);
        attr_done = true;
    }

    zero_states_kernel<<<(Bsz * Hn + 255) / 256, 256>>>();

    dim3 sgrid(Gn / 128, Bsz / 128);   // 8 x 32

    // ---- LSTM1 scan (fused gate GEMM + cell update), ping-pong h ----
    for (int v = 0; v < Vn; v++) {
        const float* hin  = (v & 1) ? h1b : h1a;
        float*       hout = (v & 1) ? h1a : h1b;
        gemm5<2, 1, 1><<<sgrid, 256, SMEMB>>>(
            hin, Hn, l1_Whh, Hn, Hn,
            state + v * Fn, Vn * Fn, l1_Wih, Fn, Fn,
            l1_bih, l1_bhh, nullptr,
            hout, Gn, c1,
            nullptr, nullptr, nullptr, nullptr, nullptr, -1);
    }
    const float* h1fin = (Vn & 1) ? h1b : h1a;

    // ---- MLP stack (relu) ----
    gemm5<1, 0, 1><<<dim3(1024 / 128, 32), 256, SMEMB>>>(
        h1fin, Hn, fc1_W, Hn, Hn,
        nullptr, 0, nullptr, 0, 0,
        fc1_b, nullptr, nullptr, m1, 1024, nullptr,
        nullptr, nullptr, nullptr, nullptr, nullptr, -1);
    gemm5<1, 0, 1><<<dim3(1024 / 128, 32), 256, SMEMB>>>(
        m1, 1024, fc2_W, 1024, 1024,
        nullptr, 0, nullptr, 0, 0,
        fc2_b, nullptr, nullptr, m2, 1024, nullptr,
        nullptr, nullptr, nullptr, nullptr, nullptr, -1);
    gemm5<1, 0, 1><<<dim3(512 / 128, 32), 256, SMEMB>>>(
        m2, 1024, fc3_W, 1024, 1024,
        nullptr, 0, nullptr, 0, 0,
        fc3_b, nullptr, nullptr, m3, 512, nullptr,
        nullptr, nullptr, nullptr, nullptr, nullptr, -1);
    gemm5<1, 0, 1><<<dim3(256 / 128, 32), 256, SMEMB>>>(
        m3, 512, fc4_W, 512, 512,
        nullptr, 0, nullptr, 0, 0,
        fc4_b, nullptr, nullptr, m4, 256, nullptr,
        nullptr, nullptr, nullptr, nullptr, nullptr, -1);

    // ---- pre2 = m4 @ Wih2[:,15:].T + bih + bhh  (REMAPPED quadrant layout) --
    gemm5<0, 1, 0><<<sgrid, 256, SMEMB>>>(
        m4, 256, l2_Wih + 15, 271, 256,
        nullptr, 0, nullptr, 0, 0,
        l2_bih, l2_bhh, nullptr, pre2, Gn, nullptr,
        nullptr, nullptr, nullptr, nullptr, nullptr, -1);

    // ---- LSTM2 scan (fused gate GEMM + cell update + pi head) ----
    const int PB = 8 * Bsz;   // per-parity pi-partial stride
    for (int v = 0; v < Vn; v++) {
        const float* hin  = (v & 1) ? h2b : h2a;
        float*       hout = (v & 1) ? h2a : h2b;
        gemm5<3, 1, 1><<<sgrid, 256, SMEMB>>>(
            hin, Hn, l2_Whh, Hn, Hn,
            state + v * Fn, Vn * Fn, l2_Wih, 271, Fn,
            nullptr, nullptr, pre2,
            hout, Gn, c2,
            pi_W, pi_b, out,
            pipart + (v & 1) * PB,
            pipart + ((v + 1) & 1) * PB,
            v - 1);
    }
    // finalize the last step's pi output
    pi_final_kernel<<<Bsz / 256, 256>>>(pipart + ((Vn - 1) & 1) * PB, pi_b, out, Vn - 1);
}